// round 1
// baseline (speedup 1.0000x reference)
#include <cuda_runtime.h>
#include <cstdint>

// Problem constants (fixed by the dataset)
#define KDIM 4096            // I (reduction dim)
#define ODIM 11008           // O (output cols)
#define KW   (ODIM / 8)      // packed words per qweight row = 1376
#define GSH  7               // log2(group_size=128)

#define BM 128
#define BN 128
#define BK 16

__device__ __forceinline__ float ftf32(float x) {
    float r;
    asm("cvt.rna.tf32.f32 %0, %1;" : "=f"(r) : "f"(x));
    return r;
}

__device__ __forceinline__ void mma_tf32(float* c, const uint32_t* a, const uint32_t* b) {
    asm volatile(
        "mma.sync.aligned.m16n8k8.row.col.f32.tf32.tf32.f32 "
        "{%0,%1,%2,%3}, {%4,%5,%6,%7}, {%8,%9}, {%0,%1,%2,%3};\n"
        : "+f"(c[0]), "+f"(c[1]), "+f"(c[2]), "+f"(c[3])
        : "r"(a[0]), "r"(a[1]), "r"(a[2]), "r"(a[3]),
          "r"(b[0]), "r"(b[1]));
}

__global__ __launch_bounds__(256)
void w4_gemm_tf32(const float* __restrict__ x,
                  const int*   __restrict__ qweight,
                  const float* __restrict__ scales,
                  const int*   __restrict__ qzeros,
                  float*       __restrict__ out,
                  int M) {
    // Shared tiles: A [BK x BM] stored as [m][k] with pad, B [BK x BN] with pad
    __shared__ float As[2][BM][BK + 1];   // stride 17 -> low-conflict frag loads
    __shared__ float Bs[2][BK][BN + 4];   // stride 132 (16B aligned) -> float4 stores OK

    const int tid  = threadIdx.x;
    const int lane = tid & 31;
    const int wid  = tid >> 5;
    const int warp_m = wid >> 2;     // 0..1 (64 rows each)
    const int warp_n = wid & 3;      // 0..3 (32 cols each)

    const int bm0 = blockIdx.y * BM;
    const int bn0 = blockIdx.x * BN;
    const int bnw = bn0 >> 3;        // packed-word column offset

    // A loader mapping: 512 float4 slots, 2 per thread
    const int ar = tid >> 2;         // row 0..63 (+64 for second)
    const int ac = (tid & 3) * 4;    // k col 0,4,8,12

    // B loader mapping: 256 words, 1 per thread
    const int br = tid >> 4;         // k row 0..15
    const int bc = tid & 15;         // word col 0..15 (8 outs each)

    float acc[4][4][4];
    #pragma unroll
    for (int i = 0; i < 4; i++)
        #pragma unroll
        for (int j = 0; j < 4; j++)
            #pragma unroll
            for (int r = 0; r < 4; r++) acc[i][j][r] = 0.0f;

    // ---- Prologue: load tile 0 into buffer 0 ----
    {
        const float* ag = x + (size_t)(bm0 + ar) * KDIM + ac;
        float4 a0 = *(const float4*)ag;
        float4 a1 = *(const float4*)(ag + (size_t)64 * KDIM);
        As[0][ar][ac + 0] = ftf32(a0.x);  As[0][ar][ac + 1] = ftf32(a0.y);
        As[0][ar][ac + 2] = ftf32(a0.z);  As[0][ar][ac + 3] = ftf32(a0.w);
        As[0][ar + 64][ac + 0] = ftf32(a1.x);  As[0][ar + 64][ac + 1] = ftf32(a1.y);
        As[0][ar + 64][ac + 2] = ftf32(a1.z);  As[0][ar + 64][ac + 3] = ftf32(a1.w);

        const int g  = 0;
        const int qw = qweight[(size_t)br * KW + bnw + bc];
        const int zw = qzeros[(size_t)g * KW + bnw + bc];
        const float* sp = scales + (size_t)g * ODIM + bn0 + bc * 8;
        float4 s0 = *(const float4*)sp;
        float4 s1 = *(const float4*)(sp + 4);
        float sv[8] = {s0.x, s0.y, s0.z, s0.w, s1.x, s1.y, s1.z, s1.w};
        #pragma unroll
        for (int j = 0; j < 8; j++) {
            int wv = (qw >> (4 * j)) & 15;
            int zv = (zw >> (4 * j)) & 15;
            Bs[0][br][bc * 8 + j] = ftf32((float)(wv - zv) * sv[j]);
        }
    }
    __syncthreads();

    const int NT = KDIM / BK;  // 256 k-tiles
    for (int t = 0; t < NT; ++t) {
        const int cur = t & 1;
        const int nxt = cur ^ 1;
        const bool has = (t + 1) < NT;
        const int k0n = (t + 1) * BK;

        // ---- Prefetch next tile from global into registers ----
        float4 a0, a1, s0, s1;
        int qw = 0, zw = 0;
        if (has) {
            const float* ag = x + (size_t)(bm0 + ar) * KDIM + k0n + ac;
            a0 = *(const float4*)ag;
            a1 = *(const float4*)(ag + (size_t)64 * KDIM);
            const int g = k0n >> GSH;
            qw = qweight[(size_t)(k0n + br) * KW + bnw + bc];
            zw = qzeros[(size_t)g * KW + bnw + bc];
            const float* sp = scales + (size_t)g * ODIM + bn0 + bc * 8;
            s0 = *(const float4*)sp;
            s1 = *(const float4*)(sp + 4);
        }

        // ---- Compute on current buffer ----
        #pragma unroll
        for (int ks = 0; ks < BK; ks += 8) {
            uint32_t af[4][4], bf[4][2];
            const int kq = lane & 3;
            const int lh = lane >> 2;
            #pragma unroll
            for (int mt = 0; mt < 4; mt++) {
                const int mr = warp_m * 64 + mt * 16 + lh;
                af[mt][0] = __float_as_uint(As[cur][mr][ks + kq]);
                af[mt][1] = __float_as_uint(As[cur][mr + 8][ks + kq]);
                af[mt][2] = __float_as_uint(As[cur][mr][ks + kq + 4]);
                af[mt][3] = __float_as_uint(As[cur][mr + 8][ks + kq + 4]);
            }
            #pragma unroll
            for (int nt = 0; nt < 4; nt++) {
                const int nc = warp_n * 32 + nt * 8 + lh;
                bf[nt][0] = __float_as_uint(Bs[cur][ks + kq][nc]);
                bf[nt][1] = __float_as_uint(Bs[cur][ks + kq + 4][nc]);
            }
            #pragma unroll
            for (int mt = 0; mt < 4; mt++)
                #pragma unroll
                for (int nt = 0; nt < 4; nt++)
                    mma_tf32(acc[mt][nt], af[mt], bf[nt]);
        }

        // ---- Store prefetched tile into next buffer ----
        if (has) {
            As[nxt][ar][ac + 0] = ftf32(a0.x);  As[nxt][ar][ac + 1] = ftf32(a0.y);
            As[nxt][ar][ac + 2] = ftf32(a0.z);  As[nxt][ar][ac + 3] = ftf32(a0.w);
            As[nxt][ar + 64][ac + 0] = ftf32(a1.x);  As[nxt][ar + 64][ac + 1] = ftf32(a1.y);
            As[nxt][ar + 64][ac + 2] = ftf32(a1.z);  As[nxt][ar + 64][ac + 3] = ftf32(a1.w);

            float sv[8] = {s0.x, s0.y, s0.z, s0.w, s1.x, s1.y, s1.z, s1.w};
            float dq[8];
            #pragma unroll
            for (int j = 0; j < 8; j++) {
                int wv = (qw >> (4 * j)) & 15;
                int zv = (zw >> (4 * j)) & 15;
                dq[j] = ftf32((float)(wv - zv) * sv[j]);
            }
            float4* bp = (float4*)&Bs[nxt][br][bc * 8];
            bp[0] = make_float4(dq[0], dq[1], dq[2], dq[3]);
            bp[1] = make_float4(dq[4], dq[5], dq[6], dq[7]);
        }
        __syncthreads();
    }

    // ---- Epilogue: write accumulators ----
    const int lh = lane >> 2;
    const int lq = lane & 3;
    #pragma unroll
    for (int mt = 0; mt < 4; mt++) {
        #pragma unroll
        for (int nt = 0; nt < 4; nt++) {
            const int row = bm0 + warp_m * 64 + mt * 16 + lh;
            const int col = bn0 + warp_n * 32 + nt * 8 + lq * 2;
            float* p = out + (size_t)row * ODIM + col;
            *(float2*)p = make_float2(acc[mt][nt][0], acc[mt][nt][1]);
            *(float2*)(p + (size_t)8 * ODIM) = make_float2(acc[mt][nt][2], acc[mt][nt][3]);
        }
    }
}

extern "C" void kernel_launch(void* const* d_in, const int* in_sizes, int n_in,
                              void* d_out, int out_size) {
    const float* x       = (const float*)d_in[0];
    const int*   qweight = (const int*)d_in[1];
    const float* scales  = (const float*)d_in[2];
    const int*   qzeros  = (const int*)d_in[3];
    float*       out     = (float*)d_out;

    const int M = in_sizes[0] / KDIM;           // 4096
    dim3 grid(ODIM / BN, M / BM);               // (86, 32)
    w4_gemm_tf32<<<grid, 256>>>(x, qweight, scales, qzeros, out, M);
}

// round 4
// speedup vs baseline: 3.7981x; 3.7981x over previous
#include <cuda_runtime.h>
#include <cuda_fp16.h>
#include <cstdint>

#define KDIM 4096
#define ODIM 11008
#define KW   1376            // ODIM/8
#define BM 128
#define BN 128
#define BKK 64
#define NSTG 64              // KDIM/BKK

#define ASZ 16384            // 128 rows x 128B (64 f16)
#define STG 32768            // A + B per stage
#define SMEM_TOTAL 65536     // 2 stages

__device__ __half g_x16[(size_t)4096 * 4096];     // x as fp16, [M][K]
__device__ __half g_w16[(size_t)11008 * 4096];    // dequant weights fp16, [O][K]

// ---------------- pre-kernel 1: x fp32 -> fp16 ----------------
__global__ __launch_bounds__(256)
void cvt_x(const float* __restrict__ x) {
    size_t i = ((size_t)blockIdx.x * 256 + threadIdx.x) * 4;
    float4 v = *(const float4*)(x + i);
    __half2 h0 = __floats2half2_rn(v.x, v.y);
    __half2 h1 = __floats2half2_rn(v.z, v.w);
    uint2 u;
    u.x = *(unsigned*)&h0;
    u.y = *(unsigned*)&h1;
    *(uint2*)(g_x16 + i) = u;
}

// ------- pre-kernel 2: dequantize weights to fp16 [O][K] -------
__global__ __launch_bounds__(256)
void dequant_w(const int* __restrict__ qweight, const float* __restrict__ scales,
               const int* __restrict__ qzeros) {
    const int w  = blockIdx.x * 32 + (threadIdx.x & 31);   // packed word col 0..1375
    const int kb = blockIdx.y * 8  + (threadIdx.x >> 5);   // k-octet 0..511
    const int g  = kb >> 4;                                // group (k/128)

    int qw[8];
    #pragma unroll
    for (int i = 0; i < 8; i++)
        qw[i] = qweight[(size_t)(kb * 8 + i) * KW + w];    // coalesced over lanes
    const int zw = qzeros[(size_t)g * KW + w];
    const float4 s0 = *(const float4*)(scales + (size_t)g * ODIM + w * 8);
    const float4 s1 = *(const float4*)(scales + (size_t)g * ODIM + w * 8 + 4);
    const float sv[8] = {s0.x, s0.y, s0.z, s0.w, s1.x, s1.y, s1.z, s1.w};

    #pragma unroll
    for (int j = 0; j < 8; j++) {                          // output col n = w*8 + j
        const int z = (zw >> (4 * j)) & 15;
        const float s = sv[j];
        uint4 u;
        unsigned* up = &u.x;
        #pragma unroll
        for (int p = 0; p < 4; p++) {
            float f0 = (float)(((qw[2 * p]     >> (4 * j)) & 15) - z) * s;
            float f1 = (float)(((qw[2 * p + 1] >> (4 * j)) & 15) - z) * s;
            __half2 h = __floats2half2_rn(f0, f1);         // low half = k even
            up[p] = *(unsigned*)&h;
        }
        *(uint4*)(g_w16 + (size_t)(w * 8 + j) * KDIM + kb * 8) = u;
    }
}

// ---------------- helpers ----------------
#define CP16(dst, src) \
    asm volatile("cp.async.cg.shared.global [%0], [%1], 16;" :: "r"(dst), "l"(src))

static __device__ __forceinline__ void ldsm_x4(unsigned* r, unsigned addr) {
    asm volatile("ldmatrix.sync.aligned.m8n8.x4.shared.b16 {%0,%1,%2,%3}, [%4];"
                 : "=r"(r[0]), "=r"(r[1]), "=r"(r[2]), "=r"(r[3]) : "r"(addr));
}
static __device__ __forceinline__ void ldsm_x2(unsigned* r, unsigned addr) {
    asm volatile("ldmatrix.sync.aligned.m8n8.x2.shared.b16 {%0,%1}, [%2];"
                 : "=r"(r[0]), "=r"(r[1]) : "r"(addr));
}
static __device__ __forceinline__ void mma_f16(float* c, const unsigned* a,
                                               const unsigned* b) {
    asm volatile(
        "mma.sync.aligned.m16n8k16.row.col.f32.f16.f16.f32 "
        "{%0,%1,%2,%3}, {%4,%5,%6,%7}, {%8,%9}, {%0,%1,%2,%3};"
        : "+f"(c[0]), "+f"(c[1]), "+f"(c[2]), "+f"(c[3])
        : "r"(a[0]), "r"(a[1]), "r"(a[2]), "r"(a[3]), "r"(b[0]), "r"(b[1]));
}

// ---------------- main fp16 GEMM ----------------
__global__ __launch_bounds__(256)
void w4_hgemm(float* __restrict__ out) {
    extern __shared__ char smem[];
    const int tid  = threadIdx.x;
    const int lane = tid & 31;
    const int wid  = tid >> 5;
    const int wm   = wid >> 2;                 // 0..1  (64 rows)
    const int wn   = wid & 3;                  // 0..3  (32 cols)
    const int bm0  = blockIdx.y * BM;
    const int bn0  = blockIdx.x * BN;

    const char* ga = (const char*)(g_x16 + (size_t)bm0 * KDIM);   // bytes
    const char* gb = (const char*)(g_w16 + (size_t)bn0 * KDIM);

    float acc[4][4][4];
    #pragma unroll
    for (int i = 0; i < 4; i++)
        #pragma unroll
        for (int j = 0; j < 4; j++)
            #pragma unroll
            for (int q = 0; q < 4; q++) acc[i][j][q] = 0.0f;

    auto issue = [&](int t) {
        char* s = smem + (t & 1) * STG;
        #pragma unroll
        for (int i = 0; i < 4; i++) {
            const int idx = tid + 256 * i;       // 1024 16B chunks per plane
            const int row = idx >> 3;            // 0..127
            const int ch  = idx & 7;             // 0..7
            const int so  = row * 128 + ((ch ^ (row & 7)) * 16);
            const size_t go = (size_t)row * 8192 + (size_t)t * 128 + ch * 16;
            unsigned da = (unsigned)__cvta_generic_to_shared(s + so);
            CP16(da, ga + go);
            unsigned db = (unsigned)__cvta_generic_to_shared(s + ASZ + so);
            CP16(db, gb + go);
        }
        asm volatile("cp.async.commit_group;");
    };

    issue(0);
    issue(1);

    const int arow = lane & 15;                 // ldmatrix x4 row-provider
    const int asel = lane >> 4;                 // 0: k-lo chunk, 1: k-hi chunk
    const int brow = lane & 7;                  // ldmatrix x2 row-provider
    const int bsel = (lane >> 3) & 1;
    const int r = lane >> 2;                    // 0..7
    const int c = lane & 3;                     // 0..3

    #pragma unroll 1
    for (int t = 0; t < NSTG; t++) {
        if (t + 1 < NSTG) asm volatile("cp.async.wait_group 1;");
        else              asm volatile("cp.async.wait_group 0;");
        __syncthreads();

        const char* As = smem + (t & 1) * STG;
        const char* Bs = As + ASZ;

        #pragma unroll
        for (int ks = 0; ks < 4; ks++) {        // 4 x k16 steps = BKK 64
            unsigned a[4][4], b[4][2];
            #pragma unroll
            for (int mt = 0; mt < 4; mt++) {
                const int row = wm * 64 + mt * 16 + arow;
                const int ch  = 2 * ks + asel;
                unsigned ad = (unsigned)__cvta_generic_to_shared(
                    As + row * 128 + ((ch ^ (row & 7)) * 16));
                ldsm_x4(a[mt], ad);
            }
            #pragma unroll
            for (int nt = 0; nt < 4; nt++) {
                const int n  = wn * 32 + nt * 8 + brow;
                const int ch = 2 * ks + bsel;
                unsigned bd = (unsigned)__cvta_generic_to_shared(
                    Bs + n * 128 + ((ch ^ (n & 7)) * 16));
                ldsm_x2(b[nt], bd);
            }
            #pragma unroll
            for (int mt = 0; mt < 4; mt++)
                #pragma unroll
                for (int nt = 0; nt < 4; nt++)
                    mma_f16(acc[mt][nt], a[mt], b[nt]);
        }
        __syncthreads();
        if (t + 2 < NSTG) issue(t + 2);
    }

    // ---- epilogue (same D-fragment layout as R1) ----
    #pragma unroll
    for (int mt = 0; mt < 4; mt++) {
        #pragma unroll
        for (int nt = 0; nt < 4; nt++) {
            const int row = bm0 + wm * 64 + mt * 16 + r;
            const int col = bn0 + wn * 32 + nt * 8 + c * 2;
            float* p = out + (size_t)row * ODIM + col;
            *(float2*)p = make_float2(acc[mt][nt][0], acc[mt][nt][1]);
            *(float2*)(p + (size_t)8 * ODIM) = make_float2(acc[mt][nt][2], acc[mt][nt][3]);
        }
    }
}

extern "C" void kernel_launch(void* const* d_in, const int* in_sizes, int n_in,
                              void* d_out, int out_size) {
    const float* x       = (const float*)d_in[0];
    const int*   qweight = (const int*)d_in[1];
    const float* scales  = (const float*)d_in[2];
    const int*   qzeros  = (const int*)d_in[3];
    float*       out     = (float*)d_out;

    const int M = in_sizes[0] / KDIM;            // 4096

    cvt_x<<<(M * KDIM) / (256 * 4), 256>>>(x);   // 16384 blocks
    dequant_w<<<dim3(KW / 32, KDIM / 64), 256>>>(qweight, scales, qzeros); // (43,64)

    cudaFuncSetAttribute(w4_hgemm, cudaFuncAttributeMaxDynamicSharedMemorySize, SMEM_TOTAL);
    dim3 grid(ODIM / BN, M / BM);                // (86, 32)
    w4_hgemm<<<grid, 256, SMEM_TOTAL>>>(out);
}